// round 2
// baseline (speedup 1.0000x reference)
#include <cuda_runtime.h>
#include <cstdint>

#define MAXN 50000
#define MAXE 1600000
#define FIN  48
#define HID  32
#define NCLS 10
#define KS   4
#define J1   160
#define NB   8

// ---------------- scratch (device globals) --------------------------------------
__device__ float    g_xw1 [MAXN * KS * HID];   // [N][4][32]
__device__ float    g_rb1 [MAXN * HID];        // x@root1 + bias1
__device__ float    g_h   [MAXN * HID];        // elu(mean+root+bias) layer-1 output
__device__ float    g_xw2 [MAXN * KS * NCLS];  // [N][4][10]
__device__ float    g_rb2 [MAXN * NCLS];       // h@root2 + bias2
__device__ int      g_cnt [MAXN];
__device__ int      g_off [MAXN + 1];
__device__ int      g_pos [MAXN];
__device__ unsigned g_esrc[MAXE];              // src | (k0<<16)
__device__ float    g_efrac[MAXE];
__device__ int      g_is64;

// ---------------- dtype detection ----------------------------------------------
__global__ void k_detect(const void* __restrict__ ei) {
    int i = threadIdx.x;
    int hi = ((const int*)ei)[2 * i + 1];
    unsigned b = __ballot_sync(0xffffffffu, hi != 0);
    if (i == 0) g_is64 = (b == 0) ? 1 : 0;
}

__global__ void k_zero_cnt(int N) {
    int i = blockIdx.x * blockDim.x + threadIdx.x;
    if (i < N) g_cnt[i] = 0;
}

// ---------------- CSR build ------------------------------------------------------
__global__ void k_hist(const void* __restrict__ ei, int E) {
    int e = blockIdx.x * blockDim.x + threadIdx.x;
    if (e >= E) return;
    int dst = g_is64 ? (int)((const long long*)ei)[(long long)E + e]
                     : ((const int*)ei)[E + e];
    atomicAdd(&g_cnt[dst], 1);
}

__global__ void k_scan(int N) {
    __shared__ int s[1024];
    int tid = threadIdx.x;
    int per = (N + 1023) / 1024;
    int base = tid * per;
    int sum = 0;
    for (int i = 0; i < per; i++) {
        int idx = base + i;
        if (idx < N) sum += g_cnt[idx];
    }
    s[tid] = sum;
    __syncthreads();
    for (int d = 1; d < 1024; d <<= 1) {
        int t = (tid >= d) ? s[tid - d] : 0;
        __syncthreads();
        s[tid] += t;
        __syncthreads();
    }
    int run = s[tid] - sum;   // exclusive prefix for this segment
    for (int i = 0; i < per; i++) {
        int idx = base + i;
        if (idx < N) {
            g_off[idx] = run;
            g_pos[idx] = run;
            run += g_cnt[idx];
        }
    }
    if (tid == 1023) g_off[N] = run;
}

__global__ void k_scatter(const void* __restrict__ ei, const float* __restrict__ ea, int E) {
    int e = blockIdx.x * blockDim.x + threadIdx.x;
    if (e >= E) return;
    int src, dst;
    if (g_is64) {
        src = (int)((const long long*)ei)[e];
        dst = (int)((const long long*)ei)[(long long)E + e];
    } else {
        src = ((const int*)ei)[e];
        dst = ((const int*)ei)[E + e];
    }
    float u = ea[e];
    float vv = u * (float)(KS - 1);
    float vf = floorf(vv);
    float frac = vv - vf;
    int k0 = min(max((int)vf, 0), KS - 1);
    int p = atomicAdd(&g_pos[dst], 1);
    g_esrc[p]  = (unsigned)src | ((unsigned)k0 << 16);
    g_efrac[p] = frac;
}

// ---------------- layer-1 node precompute ---------------------------------------
__global__ void __launch_bounds__(J1) k_xw1(const float* __restrict__ x,
                                            const float* __restrict__ W1,
                                            const float* __restrict__ root1,
                                            const float* __restrict__ bias1, int N) {
    const int j = threadIdx.x;
    float wcol[FIN];
    float binit = 0.f;
    if (j < 128) {
        int k = j >> 5, o = j & 31;
        #pragma unroll
        for (int f = 0; f < FIN; f++) wcol[f] = W1[(k * FIN + f) * HID + o];
    } else {
        int o = j - 128;
        #pragma unroll
        for (int f = 0; f < FIN; f++) wcol[f] = root1[f * HID + o];
        binit = bias1[o];
    }
    __shared__ float xs[FIN * NB];
    int ntiles = (N + NB - 1) / NB;
    for (int tile = blockIdx.x; tile < ntiles; tile += gridDim.x) {
        int n0 = tile * NB;
        __syncthreads();
        for (int idx = j; idx < FIN * NB; idx += J1) {
            int nn = idx / FIN, f = idx % FIN;
            int n = n0 + nn;
            xs[f * NB + nn] = (n < N) ? x[n * FIN + f] : 0.f;
        }
        __syncthreads();
        float acc[NB];
        #pragma unroll
        for (int nn = 0; nn < NB; nn++) acc[nn] = binit;
        #pragma unroll
        for (int f = 0; f < FIN; f++) {
            float4 xa = *(const float4*)&xs[f * NB];
            float4 xb = *(const float4*)&xs[f * NB + 4];
            float w = wcol[f];
            acc[0] += xa.x * w; acc[1] += xa.y * w; acc[2] += xa.z * w; acc[3] += xa.w * w;
            acc[4] += xb.x * w; acc[5] += xb.y * w; acc[6] += xb.z * w; acc[7] += xb.w * w;
        }
        #pragma unroll
        for (int nn = 0; nn < NB; nn++) {
            int n = n0 + nn;
            if (n < N) {
                if (j < 128) g_xw1[n * 128 + j]         = acc[nn];
                else         g_rb1[n * HID + (j - 128)] = acc[nn];
            }
        }
    }
}

// ---------------- layer-1 gather-aggregate (warp per node, fused ELU) ------------
__global__ void __launch_bounds__(256) k_agg1(int N) {
    int n = (blockIdx.x * blockDim.x + threadIdx.x) >> 5;
    int lane = threadIdx.x & 31;
    if (n >= N) return;
    int beg = g_off[n], end = g_off[n + 1];
    float acc = 0.f;
    for (int b = beg; b < end; b += 32) {
        unsigned rec = 0; float fr = 0.f;
        int e = b + lane;
        if (e < end) { rec = g_esrc[e]; fr = g_efrac[e]; }
        int cnt = min(32, end - b);
        #pragma unroll 4
        for (int i = 0; i < cnt; i++) {
            unsigned r = __shfl_sync(0xffffffffu, rec, i);
            float f    = __shfl_sync(0xffffffffu, fr, i);
            int src = r & 0xffff;
            int k0  = (r >> 16) & 3;
            int k1  = min(k0 + 1, KS - 1);
            float a  = g_xw1[src * 128 + k0 * 32 + lane];
            float bb = g_xw1[src * 128 + k1 * 32 + lane];
            acc += (1.f - f) * a + f * bb;
        }
    }
    float deg = (float)max(end - beg, 1);
    float v = acc / deg + g_rb1[n * HID + lane];
    g_h[n * HID + lane] = (v > 0.f) ? v : expm1f(v);
}

// ---------------- layer-2 node precompute (h -> xw2, rb2) ------------------------
__global__ void __launch_bounds__(64) k_prep2(const float* __restrict__ W2,
                                              const float* __restrict__ root2,
                                              const float* __restrict__ bias2, int N) {
    const int j = threadIdx.x;          // active j<50
    bool active = (j < 50);
    float wcol[HID];
    float binit = 0.f;
    if (j < 40) {
        int k = j / NCLS, c = j % NCLS;
        #pragma unroll
        for (int o = 0; o < HID; o++) wcol[o] = W2[(k * HID + o) * NCLS + c];
    } else if (j < 50) {
        int c = j - 40;
        #pragma unroll
        for (int o = 0; o < HID; o++) wcol[o] = root2[o * NCLS + c];
        binit = bias2[c];
    }
    __shared__ float hs[HID * NB];
    int ntiles = (N + NB - 1) / NB;
    for (int tile = blockIdx.x; tile < ntiles; tile += gridDim.x) {
        int n0 = tile * NB;
        __syncthreads();
        for (int idx = j; idx < HID * NB; idx += 64) {
            int nn = idx / HID, o = idx % HID;
            int n = n0 + nn;
            hs[o * NB + nn] = (n < N) ? g_h[n * HID + o] : 0.f;
        }
        __syncthreads();
        if (active) {
            float acc[NB];
            #pragma unroll
            for (int nn = 0; nn < NB; nn++) acc[nn] = binit;
            #pragma unroll
            for (int o = 0; o < HID; o++) {
                float4 ha = *(const float4*)&hs[o * NB];
                float4 hb = *(const float4*)&hs[o * NB + 4];
                float w = wcol[o];
                acc[0] += ha.x * w; acc[1] += ha.y * w; acc[2] += ha.z * w; acc[3] += ha.w * w;
                acc[4] += hb.x * w; acc[5] += hb.y * w; acc[6] += hb.z * w; acc[7] += hb.w * w;
            }
            #pragma unroll
            for (int nn = 0; nn < NB; nn++) {
                int n = n0 + nn;
                if (n < N) {
                    if (j < 40) g_xw2[n * 40 + j]          = acc[nn];
                    else        g_rb2[n * NCLS + (j - 40)] = acc[nn];
                }
            }
        }
    }
}

// ---------------- layer-2 gather-aggregate + fused log_softmax -------------------
__global__ void __launch_bounds__(256) k_agg2(float* __restrict__ out, int N) {
    int n = (blockIdx.x * blockDim.x + threadIdx.x) >> 5;
    int lane = threadIdx.x & 31;
    if (n >= N) return;
    int beg = g_off[n], end = g_off[n + 1];
    float acc = 0.f;
    for (int b = beg; b < end; b += 32) {
        unsigned rec = 0; float fr = 0.f;
        int e = b + lane;
        if (e < end) { rec = g_esrc[e]; fr = g_efrac[e]; }
        int cnt = min(32, end - b);
        #pragma unroll 4
        for (int i = 0; i < cnt; i++) {
            unsigned r = __shfl_sync(0xffffffffu, rec, i);
            float f    = __shfl_sync(0xffffffffu, fr, i);
            if (lane < NCLS) {
                int src = r & 0xffff;
                int k0  = (r >> 16) & 3;
                int k1  = min(k0 + 1, KS - 1);
                float a  = g_xw2[src * 40 + k0 * NCLS + lane];
                float bb = g_xw2[src * 40 + k1 * NCLS + lane];
                acc += (1.f - f) * a + f * bb;
            }
        }
    }
    float deg = (float)max(end - beg, 1);
    float v = -1e30f;
    if (lane < NCLS) v = acc / deg + g_rb2[n * NCLS + lane];
    // warp log_softmax over 10 lanes
    float mx = v;
    #pragma unroll
    for (int d = 16; d > 0; d >>= 1) mx = fmaxf(mx, __shfl_xor_sync(0xffffffffu, mx, d));
    float ex = (lane < NCLS) ? expf(v - mx) : 0.f;
    float s = ex;
    #pragma unroll
    for (int d = 16; d > 0; d >>= 1) s += __shfl_xor_sync(0xffffffffu, s, d);
    float ls = logf(s) + mx;
    if (lane < NCLS) out[n * NCLS + lane] = v - ls;
}

// ---------------- launch ----------------------------------------------------------
extern "C" void kernel_launch(void* const* d_in, const int* in_sizes, int n_in,
                              void* d_out, int out_size) {
    const float* x     = (const float*)d_in[0];
    const void*  ei    =               d_in[1];
    const float* ea    = (const float*)d_in[2];
    const float* W1    = (const float*)d_in[3];
    const float* root1 = (const float*)d_in[4];
    const float* bias1 = (const float*)d_in[5];
    const float* W2    = (const float*)d_in[6];
    const float* root2 = (const float*)d_in[7];
    const float* bias2 = (const float*)d_in[8];
    float* out = (float*)d_out;

    int N = in_sizes[0] / FIN;     // 50000
    int E = in_sizes[2];           // 1600000

    int egrid = (E + 255) / 256;
    k_detect<<<1, 32>>>(ei);
    k_zero_cnt<<<(N + 255) / 256, 256>>>(N);
    k_hist<<<egrid, 256>>>(ei, E);
    k_scan<<<1, 1024>>>(N);
    k_scatter<<<egrid, 256>>>(ei, ea, E);
    k_xw1<<<592, J1>>>(x, W1, root1, bias1, N);
    int agrid = (N * 32 + 255) / 256;
    k_agg1<<<agrid, 256>>>(N);
    k_prep2<<<1184, 64>>>(W2, root2, bias2, N);
    k_agg2<<<agrid, 256>>>(out, N);
}

// round 3
// speedup vs baseline: 1.2917x; 1.2917x over previous
#include <cuda_runtime.h>
#include <cstdint>

#define MAXN 50000
#define MAXE 1600000
#define FIN  48
#define HID  32
#define NCLS 10
#define KS   4
#define J1   160
#define NB   8
#define SBLK 256
#define NSCB ((MAXN + SBLK - 1) / SBLK)   // 196

// ---------------- scratch (device globals) --------------------------------------
__device__ float    g_xw1 [MAXN * KS * HID];   // [N][4][32]
__device__ float    g_rb1 [MAXN * HID];
__device__ float    g_h   [MAXN * HID];
__device__ float    g_xw2 [MAXN * KS * NCLS];  // [N][4][10]
__device__ float    g_rb2 [MAXN * NCLS];
__device__ int      g_cnt [MAXN];
__device__ int      g_off [MAXN + 1];
__device__ int      g_pos [MAXN];
__device__ int      g_part[NSCB];
__device__ unsigned g_erec[MAXE];              // src | k0<<16 | q14<<18
__device__ int      g_is64;

// ---------------- dtype detection ----------------------------------------------
__global__ void k_detect(const void* __restrict__ ei) {
    int i = threadIdx.x;
    int hi = ((const int*)ei)[2 * i + 1];
    unsigned b = __ballot_sync(0xffffffffu, hi != 0);
    if (i == 0) g_is64 = (b == 0) ? 1 : 0;
}

__global__ void k_zero_cnt(int N) {
    int i = blockIdx.x * blockDim.x + threadIdx.x;
    if (i < N) g_cnt[i] = 0;
}

// ---------------- CSR build ------------------------------------------------------
__global__ void k_hist(const void* __restrict__ ei, int E) {
    int e = blockIdx.x * blockDim.x + threadIdx.x;
    if (e >= E) return;
    int dst = g_is64 ? (int)((const long long*)ei)[(long long)E + e]
                     : ((const int*)ei)[E + e];
    atomicAdd(&g_cnt[dst], 1);
}

// stage 1: per-block sums of g_cnt
__global__ void __launch_bounds__(SBLK) k_scan1(int N) {
    __shared__ int s[SBLK];
    int i = blockIdx.x * SBLK + threadIdx.x;
    int c = (i < N) ? g_cnt[i] : 0;
    s[threadIdx.x] = c;
    __syncthreads();
    for (int d = SBLK / 2; d > 0; d >>= 1) {
        if (threadIdx.x < d) s[threadIdx.x] += s[threadIdx.x + d];
        __syncthreads();
    }
    if (threadIdx.x == 0) g_part[blockIdx.x] = s[0];
}

// stage 2: exclusive scan of partials (nb <= 256) + tail offset
__global__ void __launch_bounds__(SBLK) k_scan2(int nb, int N, int E) {
    __shared__ int s[SBLK];
    int tid = threadIdx.x;
    int own = (tid < nb) ? g_part[tid] : 0;
    s[tid] = own;
    __syncthreads();
    for (int d = 1; d < SBLK; d <<= 1) {
        int t = (tid >= d) ? s[tid - d] : 0;
        __syncthreads();
        s[tid] += t;
        __syncthreads();
    }
    if (tid < nb) g_part[tid] = s[tid] - own;   // exclusive
    if (tid == 0) g_off[N] = E;
}

// stage 3: per-block exclusive rescan + base offset
__global__ void __launch_bounds__(SBLK) k_scan3(int N) {
    __shared__ int s[SBLK];
    int tid = threadIdx.x;
    int i = blockIdx.x * SBLK + tid;
    int c = (i < N) ? g_cnt[i] : 0;
    s[tid] = c;
    __syncthreads();
    for (int d = 1; d < SBLK; d <<= 1) {
        int t = (tid >= d) ? s[tid - d] : 0;
        __syncthreads();
        s[tid] += t;
        __syncthreads();
    }
    if (i < N) {
        int val = g_part[blockIdx.x] + s[tid] - c;
        g_off[i] = val;
        g_pos[i] = val;
    }
}

__global__ void k_scatter(const void* __restrict__ ei, const float* __restrict__ ea, int E) {
    int e = blockIdx.x * blockDim.x + threadIdx.x;
    if (e >= E) return;
    int src, dst;
    if (g_is64) {
        src = (int)((const long long*)ei)[e];
        dst = (int)((const long long*)ei)[(long long)E + e];
    } else {
        src = ((const int*)ei)[e];
        dst = ((const int*)ei)[E + e];
    }
    float u = ea[e];
    float vv = u * (float)(KS - 1);
    float vf = floorf(vv);
    float frac = vv - vf;
    int k0 = min(max((int)vf, 0), KS - 1);
    unsigned q = (unsigned)__float2uint_rn(frac * 16383.f);
    int p = atomicAdd(&g_pos[dst], 1);
    g_erec[p] = (unsigned)src | ((unsigned)k0 << 16) | (q << 18);
}

// ---------------- layer-1 node precompute ---------------------------------------
__global__ void __launch_bounds__(J1) k_xw1(const float* __restrict__ x,
                                            const float* __restrict__ W1,
                                            const float* __restrict__ root1,
                                            const float* __restrict__ bias1, int N) {
    const int j = threadIdx.x;
    float wcol[FIN];
    float binit = 0.f;
    if (j < 128) {
        int k = j >> 5, o = j & 31;
        #pragma unroll
        for (int f = 0; f < FIN; f++) wcol[f] = W1[(k * FIN + f) * HID + o];
    } else {
        int o = j - 128;
        #pragma unroll
        for (int f = 0; f < FIN; f++) wcol[f] = root1[f * HID + o];
        binit = bias1[o];
    }
    __shared__ float xs[FIN * NB];
    int ntiles = (N + NB - 1) / NB;
    for (int tile = blockIdx.x; tile < ntiles; tile += gridDim.x) {
        int n0 = tile * NB;
        __syncthreads();
        for (int idx = j; idx < FIN * NB; idx += J1) {
            int nn = idx / FIN, f = idx % FIN;
            int n = n0 + nn;
            xs[f * NB + nn] = (n < N) ? x[n * FIN + f] : 0.f;
        }
        __syncthreads();
        float acc[NB];
        #pragma unroll
        for (int nn = 0; nn < NB; nn++) acc[nn] = binit;
        #pragma unroll
        for (int f = 0; f < FIN; f++) {
            float4 xa = *(const float4*)&xs[f * NB];
            float4 xb = *(const float4*)&xs[f * NB + 4];
            float w = wcol[f];
            acc[0] += xa.x * w; acc[1] += xa.y * w; acc[2] += xa.z * w; acc[3] += xa.w * w;
            acc[4] += xb.x * w; acc[5] += xb.y * w; acc[6] += xb.z * w; acc[7] += xb.w * w;
        }
        #pragma unroll
        for (int nn = 0; nn < NB; nn++) {
            int n = n0 + nn;
            if (n < N) {
                if (j < 128) g_xw1[n * 128 + j]         = acc[nn];
                else         g_rb1[n * HID + (j - 128)] = acc[nn];
            }
        }
    }
}

// ---------------- layer-1 gather-aggregate (warp per node, fused ELU) ------------
__global__ void __launch_bounds__(256) k_agg1(int N) {
    int n = (blockIdx.x * blockDim.x + threadIdx.x) >> 5;
    int lane = threadIdx.x & 31;
    if (n >= N) return;
    int beg = g_off[n], end = g_off[n + 1];
    float acc = 0.f;
    for (int b = beg; b < end; b += 32) {
        unsigned rec = 0;
        int e = b + lane;
        if (e < end) rec = g_erec[e];
        int cnt = min(32, end - b);
        #pragma unroll 4
        for (int i = 0; i < cnt; i++) {
            unsigned r = __shfl_sync(0xffffffffu, rec, i);
            int src = r & 0xffff;
            int k0  = (r >> 16) & 3;
            int k1  = min(k0 + 1, KS - 1);
            float f = (float)(r >> 18) * (1.f / 16383.f);
            float a  = g_xw1[src * 128 + k0 * 32 + lane];
            float bb = g_xw1[src * 128 + k1 * 32 + lane];
            acc += (1.f - f) * a + f * bb;
        }
    }
    float deg = (float)max(end - beg, 1);
    float v = acc / deg + g_rb1[n * HID + lane];
    g_h[n * HID + lane] = (v > 0.f) ? v : expm1f(v);
}

// ---------------- layer-2 node precompute ----------------------------------------
__global__ void __launch_bounds__(64) k_prep2(const float* __restrict__ W2,
                                              const float* __restrict__ root2,
                                              const float* __restrict__ bias2, int N) {
    const int j = threadIdx.x;          // active j<50
    bool active = (j < 50);
    float wcol[HID];
    float binit = 0.f;
    if (j < 40) {
        int k = j / NCLS, c = j % NCLS;
        #pragma unroll
        for (int o = 0; o < HID; o++) wcol[o] = W2[(k * HID + o) * NCLS + c];
    } else if (j < 50) {
        int c = j - 40;
        #pragma unroll
        for (int o = 0; o < HID; o++) wcol[o] = root2[o * NCLS + c];
        binit = bias2[c];
    }
    __shared__ float hs[HID * NB];
    int ntiles = (N + NB - 1) / NB;
    for (int tile = blockIdx.x; tile < ntiles; tile += gridDim.x) {
        int n0 = tile * NB;
        __syncthreads();
        for (int idx = j; idx < HID * NB; idx += 64) {
            int nn = idx / HID, o = idx % HID;
            int n = n0 + nn;
            hs[o * NB + nn] = (n < N) ? g_h[n * HID + o] : 0.f;
        }
        __syncthreads();
        if (active) {
            float acc[NB];
            #pragma unroll
            for (int nn = 0; nn < NB; nn++) acc[nn] = binit;
            #pragma unroll
            for (int o = 0; o < HID; o++) {
                float4 ha = *(const float4*)&hs[o * NB];
                float4 hb = *(const float4*)&hs[o * NB + 4];
                float w = wcol[o];
                acc[0] += ha.x * w; acc[1] += ha.y * w; acc[2] += ha.z * w; acc[3] += ha.w * w;
                acc[4] += hb.x * w; acc[5] += hb.y * w; acc[6] += hb.z * w; acc[7] += hb.w * w;
            }
            #pragma unroll
            for (int nn = 0; nn < NB; nn++) {
                int n = n0 + nn;
                if (n < N) {
                    if (j < 40) g_xw2[n * 40 + j]          = acc[nn];
                    else        g_rb2[n * NCLS + (j - 40)] = acc[nn];
                }
            }
        }
    }
}

// ---------------- layer-2 gather-aggregate + fused log_softmax -------------------
__global__ void __launch_bounds__(256) k_agg2(float* __restrict__ out, int N) {
    int n = (blockIdx.x * blockDim.x + threadIdx.x) >> 5;
    int lane = threadIdx.x & 31;
    if (n >= N) return;
    int beg = g_off[n], end = g_off[n + 1];
    float acc = 0.f;
    for (int b = beg; b < end; b += 32) {
        unsigned rec = 0;
        int e = b + lane;
        if (e < end) rec = g_erec[e];
        int cnt = min(32, end - b);
        #pragma unroll 4
        for (int i = 0; i < cnt; i++) {
            unsigned r = __shfl_sync(0xffffffffu, rec, i);
            if (lane < NCLS) {
                int src = r & 0xffff;
                int k0  = (r >> 16) & 3;
                int k1  = min(k0 + 1, KS - 1);
                float f = (float)(r >> 18) * (1.f / 16383.f);
                float a  = g_xw2[src * 40 + k0 * NCLS + lane];
                float bb = g_xw2[src * 40 + k1 * NCLS + lane];
                acc += (1.f - f) * a + f * bb;
            }
        }
    }
    float deg = (float)max(end - beg, 1);
    float v = -1e30f;
    if (lane < NCLS) v = acc / deg + g_rb2[n * NCLS + lane];
    float mx = v;
    #pragma unroll
    for (int d = 16; d > 0; d >>= 1) mx = fmaxf(mx, __shfl_xor_sync(0xffffffffu, mx, d));
    float ex = (lane < NCLS) ? expf(v - mx) : 0.f;
    float s = ex;
    #pragma unroll
    for (int d = 16; d > 0; d >>= 1) s += __shfl_xor_sync(0xffffffffu, s, d);
    float ls = logf(s) + mx;
    if (lane < NCLS) out[n * NCLS + lane] = v - ls;
}

// ---------------- launch ----------------------------------------------------------
extern "C" void kernel_launch(void* const* d_in, const int* in_sizes, int n_in,
                              void* d_out, int out_size) {
    const float* x     = (const float*)d_in[0];
    const void*  ei    =               d_in[1];
    const float* ea    = (const float*)d_in[2];
    const float* W1    = (const float*)d_in[3];
    const float* root1 = (const float*)d_in[4];
    const float* bias1 = (const float*)d_in[5];
    const float* W2    = (const float*)d_in[6];
    const float* root2 = (const float*)d_in[7];
    const float* bias2 = (const float*)d_in[8];
    float* out = (float*)d_out;

    int N = in_sizes[0] / FIN;     // 50000
    int E = in_sizes[2];           // 1600000
    int nb = (N + SBLK - 1) / SBLK;

    int egrid = (E + 255) / 256;
    k_detect<<<1, 32>>>(ei);
    k_zero_cnt<<<(N + 255) / 256, 256>>>(N);
    k_hist<<<egrid, 256>>>(ei, E);
    k_scan1<<<nb, SBLK>>>(N);
    k_scan2<<<1, SBLK>>>(nb, N, E);
    k_scan3<<<nb, SBLK>>>(N);
    k_scatter<<<egrid, 256>>>(ei, ea, E);
    k_xw1<<<592, J1>>>(x, W1, root1, bias1, N);
    int agrid = (N * 32 + 255) / 256;
    k_agg1<<<agrid, 256>>>(N);
    k_prep2<<<1184, 64>>>(W2, root2, bias2, N);
    k_agg2<<<agrid, 256>>>(out, N);
}

// round 4
// speedup vs baseline: 1.8254x; 1.4132x over previous
#include <cuda_runtime.h>
#include <cuda_fp16.h>
#include <cstdint>

#define MAXN 50000
#define MAXE 1600000
#define FIN  48
#define HID  32
#define NCLS 10
#define KS   4
#define J1   160
#define NB   16

// ---------------- scratch (device globals) --------------------------------------
__device__ __half    g_xw1h[MAXN * KS * HID];   // [N][4][32] fp16
__device__ float     g_rb1 [MAXN * HID];        // x@root1 + bias1 (fp32)
__device__ __half    g_xw2h[MAXN * KS * NCLS];  // [N][4][10] fp16
__device__ float     g_rb2 [MAXN * NCLS];
__device__ float     g_agg1[MAXN * HID];
__device__ float     g_agg2[MAXN * NCLS];
__device__ float     g_deg [MAXN];
__device__ uint2     g_pack[MAXE];              // x: src|dst<<16,  y: frac-bits|k0
__device__ int       g_is64;

// ---------------- helpers ---------------------------------------------------------
__device__ __forceinline__ void red_add_v4(float* addr, float4 v) {
    asm volatile("red.global.add.v4.f32 [%0], {%1,%2,%3,%4};"
                 :: "l"(addr), "f"(v.x), "f"(v.y), "f"(v.z), "f"(v.w) : "memory");
}
__device__ __forceinline__ void red_add_v2(float* addr, float2 v) {
    asm volatile("red.global.add.v2.f32 [%0], {%1,%2};"
                 :: "l"(addr), "f"(v.x), "f"(v.y) : "memory");
}

// ---------------- dtype detection -------------------------------------------------
__global__ void k_detect(const void* __restrict__ ei) {
    int i = threadIdx.x;
    int hi = ((const int*)ei)[2 * i + 1];
    unsigned b = __ballot_sync(0xffffffffu, hi != 0);
    if (i == 0) g_is64 = (b == 0) ? 1 : 0;
}

// ---------------- zero agg1, agg2, deg --------------------------------------------
__global__ void k_zero(int N) {
    int tot = N * (HID + NCLS + 1);
    for (int i = blockIdx.x * blockDim.x + threadIdx.x; i < tot; i += gridDim.x * blockDim.x) {
        if (i < N * HID)              g_agg1[i] = 0.f;
        else if (i < N * (HID + NCLS)) g_agg2[i - N * HID] = 0.f;
        else                          g_deg[i - N * (HID + NCLS)] = 0.f;
    }
}

// ---------------- pack edges: decode once, also accumulate degree ------------------
__global__ void __launch_bounds__(256) k_pack(const void* __restrict__ ei,
                                              const float* __restrict__ ea, int E) {
    int e = blockIdx.x * blockDim.x + threadIdx.x;
    if (e >= E) return;
    int src, dst;
    if (g_is64) {
        src = (int)((const long long*)ei)[e];
        dst = (int)((const long long*)ei)[(long long)E + e];
    } else {
        src = ((const int*)ei)[e];
        dst = ((const int*)ei)[E + e];
    }
    float u = ea[e];
    float vv = u * (float)(KS - 1);
    float vf = floorf(vv);
    float frac = vv - vf;
    int k0 = min(max((int)vf, 0), KS - 1);
    g_pack[e] = make_uint2((unsigned)src | ((unsigned)dst << 16),
                           (__float_as_uint(frac) & ~3u) | (unsigned)k0);
    atomicAdd(&g_deg[dst], 1.0f);
}

// ---------------- layer-1 node GEMM: xw1 (fp16 out), rb1 (fp32) -------------------
__global__ void __launch_bounds__(J1) k_xw1(const float* __restrict__ x,
                                            const float* __restrict__ W1,
                                            const float* __restrict__ root1,
                                            const float* __restrict__ bias1, int N) {
    const int j = threadIdx.x;
    float wcol[FIN];
    float binit = 0.f;
    if (j < 128) {
        int k = j >> 5, o = j & 31;
        #pragma unroll
        for (int f = 0; f < FIN; f++) wcol[f] = W1[(k * FIN + f) * HID + o];
    } else {
        int o = j - 128;
        #pragma unroll
        for (int f = 0; f < FIN; f++) wcol[f] = root1[f * HID + o];
        binit = bias1[o];
    }
    __shared__ float xs[FIN * NB];
    int ntiles = (N + NB - 1) / NB;
    for (int tile = blockIdx.x; tile < ntiles; tile += gridDim.x) {
        int n0 = tile * NB;
        __syncthreads();
        for (int idx = j; idx < FIN * NB; idx += J1) {
            int nn = idx / FIN, f = idx % FIN;
            int n = n0 + nn;
            xs[f * NB + nn] = (n < N) ? x[n * FIN + f] : 0.f;
        }
        __syncthreads();
        float acc[NB];
        #pragma unroll
        for (int nn = 0; nn < NB; nn++) acc[nn] = binit;
        #pragma unroll
        for (int f = 0; f < FIN; f++) {
            float w = wcol[f];
            #pragma unroll
            for (int q = 0; q < NB / 4; q++) {
                float4 xa = *(const float4*)&xs[f * NB + q * 4];
                acc[q*4+0] += xa.x * w; acc[q*4+1] += xa.y * w;
                acc[q*4+2] += xa.z * w; acc[q*4+3] += xa.w * w;
            }
        }
        #pragma unroll
        for (int nn = 0; nn < NB; nn++) {
            int n = n0 + nn;
            if (n < N) {
                if (j < 128) g_xw1h[n * 128 + j]        = __float2half(acc[nn]);
                else         g_rb1[n * HID + (j - 128)] = acc[nn];
            }
        }
    }
}

// ---------------- layer-1 edge scatter: 8 lanes/edge, fp16 gather, fp32 red -------
__global__ void __launch_bounds__(256) k_edge1(int E) {
    long long t = (long long)blockIdx.x * blockDim.x + threadIdx.x;
    long long e = t >> 3;
    int f4 = (int)(t & 7);
    if (e >= E) return;
    uint2 r = g_pack[e];
    int src = r.x & 0xffff;
    int dst = r.x >> 16;
    int k0  = r.y & 3;
    int k1  = min(k0 + 1, KS - 1);
    float f = __uint_as_float(r.y & ~3u);
    const __half* base = g_xw1h + src * 128;
    uint2 pa = *(const uint2*)(base + k0 * 32 + f4 * 4);
    uint2 pb = *(const uint2*)(base + k1 * 32 + f4 * 4);
    float2 A0 = __half22float2(*(const __half2*)&pa.x);
    float2 A1 = __half22float2(*(const __half2*)&pa.y);
    float2 B0 = __half22float2(*(const __half2*)&pb.x);
    float2 B1 = __half22float2(*(const __half2*)&pb.y);
    float w0 = 1.0f - f;
    float4 m = make_float4(w0 * A0.x + f * B0.x, w0 * A0.y + f * B0.y,
                           w0 * A1.x + f * B1.x, w0 * A1.y + f * B1.y);
    red_add_v4(&g_agg1[dst * HID + f4 * 4], m);
}

// ---------------- layer-2 node GEMM (fused layer-1 epilogue) ----------------------
__global__ void __launch_bounds__(64) k_prep2(const float* __restrict__ W2,
                                              const float* __restrict__ root2,
                                              const float* __restrict__ bias2, int N) {
    const int j = threadIdx.x;          // active j<50
    bool active = (j < 50);
    float wcol[HID];
    float binit = 0.f;
    if (j < 40) {
        int k = j / NCLS, c = j % NCLS;
        #pragma unroll
        for (int o = 0; o < HID; o++) wcol[o] = W2[(k * HID + o) * NCLS + c];
    } else if (j < 50) {
        int c = j - 40;
        #pragma unroll
        for (int o = 0; o < HID; o++) wcol[o] = root2[o * NCLS + c];
        binit = bias2[c];
    }
    __shared__ float hs[HID * NB];
    int ntiles = (N + NB - 1) / NB;
    for (int tile = blockIdx.x; tile < ntiles; tile += gridDim.x) {
        int n0 = tile * NB;
        __syncthreads();
        for (int idx = j; idx < HID * NB; idx += 64) {
            int nn = idx / HID, o = idx % HID;
            int n = n0 + nn;
            float h = 0.f;
            if (n < N) {
                float d = fmaxf(g_deg[n], 1.0f);
                float v = g_agg1[n * HID + o] / d + g_rb1[n * HID + o];
                h = (v > 0.f) ? v : expm1f(v);
            }
            hs[o * NB + nn] = h;
        }
        __syncthreads();
        if (active) {
            float acc[NB];
            #pragma unroll
            for (int nn = 0; nn < NB; nn++) acc[nn] = binit;
            #pragma unroll
            for (int o = 0; o < HID; o++) {
                float w = wcol[o];
                #pragma unroll
                for (int q = 0; q < NB / 4; q++) {
                    float4 ha = *(const float4*)&hs[o * NB + q * 4];
                    acc[q*4+0] += ha.x * w; acc[q*4+1] += ha.y * w;
                    acc[q*4+2] += ha.z * w; acc[q*4+3] += ha.w * w;
                }
            }
            #pragma unroll
            for (int nn = 0; nn < NB; nn++) {
                int n = n0 + nn;
                if (n < N) {
                    if (j < 40) g_xw2h[n * 40 + j]         = __float2half(acc[nn]);
                    else        g_rb2[n * NCLS + (j - 40)] = acc[nn];
                }
            }
        }
    }
}

// ---------------- layer-2 edge scatter: 6 edges/warp x 5 lanes (float2) -----------
__global__ void __launch_bounds__(256) k_edge2(int E) {
    int t = blockIdx.x * blockDim.x + threadIdx.x;
    int lane = t & 31;
    int wid = t >> 5;
    int eg = lane / 5;
    int j  = lane - eg * 5;
    if (eg >= 6) return;                 // lanes 30,31 idle
    long long e = (long long)wid * 6 + eg;
    if (e >= E) return;
    uint2 r = g_pack[e];
    int src = r.x & 0xffff;
    int dst = r.x >> 16;
    int k0  = r.y & 3;
    int k1  = min(k0 + 1, KS - 1);
    float f = __uint_as_float(r.y & ~3u);
    const __half* base = g_xw2h + src * 40;
    unsigned pa = *(const unsigned*)(base + k0 * 10 + j * 2);
    unsigned pb = *(const unsigned*)(base + k1 * 10 + j * 2);
    float2 A = __half22float2(*(const __half2*)&pa);
    float2 B = __half22float2(*(const __half2*)&pb);
    float w0 = 1.0f - f;
    float2 m = make_float2(w0 * A.x + f * B.x, w0 * A.y + f * B.y);
    red_add_v2(&g_agg2[dst * NCLS + j * 2], m);
}

// ---------------- final: mean + root + bias + log_softmax -------------------------
__global__ void k_out(float* __restrict__ out, int N) {
    int n = blockIdx.x * blockDim.x + threadIdx.x;
    if (n >= N) return;
    float inv = 1.0f / fmaxf(g_deg[n], 1.0f);
    float v[NCLS];
    float mx = -1e30f;
    #pragma unroll
    for (int c = 0; c < NCLS; c++) {
        v[c] = g_agg2[n * NCLS + c] * inv + g_rb2[n * NCLS + c];
        mx = fmaxf(mx, v[c]);
    }
    float s = 0.f;
    #pragma unroll
    for (int c = 0; c < NCLS; c++) s += expf(v[c] - mx);
    float ls = logf(s) + mx;
    #pragma unroll
    for (int c = 0; c < NCLS; c++) out[n * NCLS + c] = v[c] - ls;
}

// ---------------- launch -----------------------------------------------------------
extern "C" void kernel_launch(void* const* d_in, const int* in_sizes, int n_in,
                              void* d_out, int out_size) {
    const float* x     = (const float*)d_in[0];
    const void*  ei    =               d_in[1];
    const float* ea    = (const float*)d_in[2];
    const float* W1    = (const float*)d_in[3];
    const float* root1 = (const float*)d_in[4];
    const float* bias1 = (const float*)d_in[5];
    const float* W2    = (const float*)d_in[6];
    const float* root2 = (const float*)d_in[7];
    const float* bias2 = (const float*)d_in[8];
    float* out = (float*)d_out;

    int N = in_sizes[0] / FIN;     // 50000
    int E = in_sizes[2];           // 1600000

    k_detect<<<1, 32>>>(ei);
    k_zero<<<(N * (HID + NCLS + 1) + 255) / 256, 256>>>(N);
    k_pack<<<(E + 255) / 256, 256>>>(ei, ea, E);
    k_xw1<<<592, J1>>>(x, W1, root1, bias1, N);
    long long th1 = (long long)E * 8;
    k_edge1<<<(int)((th1 + 255) / 256), 256>>>(E);
    k_prep2<<<1184, 64>>>(W2, root2, bias2, N);
    int warps2 = (E + 5) / 6;
    k_edge2<<<(warps2 + 7) / 8, 256>>>(E);
    k_out<<<(N + 255) / 256, 256>>>(out, N);
}

// round 5
// speedup vs baseline: 1.8992x; 1.0404x over previous
#include <cuda_runtime.h>
#include <cuda_fp16.h>
#include <cstdint>

#define MAXN 50000
#define MAXE 1600000
#define FIN  48
#define HID  32
#define NCLS 10
#define KS   4
#define J1   160
#define NB   16

// ---------------- scratch (device globals) --------------------------------------
__device__ __half    g_xw1h[MAXN * KS * HID];   // [N][4][32] fp16
__device__ float     g_rb1 [MAXN * HID];        // x@root1 + bias1 (fp32)
__device__ __half    g_xw2h[MAXN * KS * NCLS];  // [N][4][10] fp16
__device__ float     g_rb2 [MAXN * NCLS];
__device__ float     g_agg1[MAXN * HID];
__device__ float     g_agg2[MAXN * NCLS];
__device__ float     g_h   [MAXN * HID];
__device__ float     g_deg [MAXN];
__device__ uint2     g_pack[MAXE];              // x: src|dst<<16,  y: frac-bits|k0
__device__ int       g_is64;

// ---------------- helpers ---------------------------------------------------------
__device__ __forceinline__ void red_add_v4(float* addr, float4 v) {
    asm volatile("red.global.add.v4.f32 [%0], {%1,%2,%3,%4};"
                 :: "l"(addr), "f"(v.x), "f"(v.y), "f"(v.z), "f"(v.w) : "memory");
}
__device__ __forceinline__ void red_add_v2(float* addr, float2 v) {
    asm volatile("red.global.add.v2.f32 [%0], {%1,%2};"
                 :: "l"(addr), "f"(v.x), "f"(v.y) : "memory");
}
__device__ __forceinline__ unsigned long long pack2(float w) {
    unsigned long long r;
    asm("mov.b64 %0, {%1, %1};" : "=l"(r) : "f"(w));
    return r;
}
__device__ __forceinline__ void ffma2(unsigned long long& d, unsigned long long a,
                                      unsigned long long b) {
    asm("fma.rn.f32x2 %0, %1, %2, %0;" : "+l"(d) : "l"(a), "l"(b));
}
__device__ __forceinline__ float2 unpack2(unsigned long long v) {
    float lo, hi;
    asm("mov.b64 {%0, %1}, %2;" : "=f"(lo), "=f"(hi) : "l"(v));
    return make_float2(lo, hi);
}

// ---------------- dtype detection -------------------------------------------------
__global__ void k_detect(const void* __restrict__ ei) {
    int i = threadIdx.x;
    int hi = ((const int*)ei)[2 * i + 1];
    unsigned b = __ballot_sync(0xffffffffu, hi != 0);
    if (i == 0) g_is64 = (b == 0) ? 1 : 0;
}

// ---------------- zero agg1, agg2, deg --------------------------------------------
__global__ void k_zero(int N) {
    int tot = N * (HID + NCLS + 1);
    for (int i = blockIdx.x * blockDim.x + threadIdx.x; i < tot; i += gridDim.x * blockDim.x) {
        if (i < N * HID)               g_agg1[i] = 0.f;
        else if (i < N * (HID + NCLS)) g_agg2[i - N * HID] = 0.f;
        else                           g_deg[i - N * (HID + NCLS)] = 0.f;
    }
}

// ---------------- pack edges: decode once, also accumulate degree ------------------
__global__ void __launch_bounds__(256) k_pack(const void* __restrict__ ei,
                                              const float* __restrict__ ea, int E) {
    int e = blockIdx.x * blockDim.x + threadIdx.x;
    if (e >= E) return;
    int src, dst;
    if (g_is64) {
        src = (int)((const long long*)ei)[e];
        dst = (int)((const long long*)ei)[(long long)E + e];
    } else {
        src = ((const int*)ei)[e];
        dst = ((const int*)ei)[E + e];
    }
    float u = ea[e];
    float vv = u * (float)(KS - 1);
    float vf = floorf(vv);
    float frac = vv - vf;
    int k0 = min(max((int)vf, 0), KS - 1);
    g_pack[e] = make_uint2((unsigned)src | ((unsigned)dst << 16),
                           (__float_as_uint(frac) & ~3u) | (unsigned)k0);
    atomicAdd(&g_deg[dst], 1.0f);
}

// ---------------- layer-1 node GEMM (f32x2): xw1 fp16, rb1 fp32 -------------------
__global__ void __launch_bounds__(J1) k_xw1(const float* __restrict__ x,
                                            const float* __restrict__ W1,
                                            const float* __restrict__ root1,
                                            const float* __restrict__ bias1, int N) {
    const int j = threadIdx.x;
    float wcol[FIN];
    float binit = 0.f;
    if (j < 128) {
        int k = j >> 5, o = j & 31;
        #pragma unroll
        for (int f = 0; f < FIN; f++) wcol[f] = W1[(k * FIN + f) * HID + o];
    } else {
        int o = j - 128;
        #pragma unroll
        for (int f = 0; f < FIN; f++) wcol[f] = root1[f * HID + o];
        binit = bias1[o];
    }
    __shared__ __align__(16) float xs[FIN * NB];
    int ntiles = (N + NB - 1) / NB;
    for (int tile = blockIdx.x; tile < ntiles; tile += gridDim.x) {
        int n0 = tile * NB;
        __syncthreads();
        for (int idx = j; idx < FIN * NB; idx += J1) {
            int nn = idx / FIN, f = idx % FIN;
            int n = n0 + nn;
            xs[f * NB + nn] = (n < N) ? x[n * FIN + f] : 0.f;
        }
        __syncthreads();
        unsigned long long acc2[NB / 2];
        unsigned long long binit2 = pack2(binit);
        #pragma unroll
        for (int p = 0; p < NB / 2; p++) acc2[p] = binit2;
        #pragma unroll
        for (int f = 0; f < FIN; f++) {
            unsigned long long w2 = pack2(wcol[f]);
            #pragma unroll
            for (int q = 0; q < NB / 4; q++) {
                ulonglong2 xv = *(const ulonglong2*)&xs[f * NB + q * 4];
                ffma2(acc2[q * 2],     xv.x, w2);
                ffma2(acc2[q * 2 + 1], xv.y, w2);
            }
        }
        #pragma unroll
        for (int p = 0; p < NB / 2; p++) {
            float2 v = unpack2(acc2[p]);
            int na = n0 + p * 2, nb2 = na + 1;
            if (na < N) {
                if (j < 128) g_xw1h[na * 128 + j]        = __float2half(v.x);
                else         g_rb1[na * HID + (j - 128)] = v.x;
            }
            if (nb2 < N) {
                if (j < 128) g_xw1h[nb2 * 128 + j]        = __float2half(v.y);
                else         g_rb1[nb2 * HID + (j - 128)] = v.y;
            }
        }
    }
}

// ---------------- layer-1 edge scatter: 8 lanes/edge, fp16 gather, fp32 red -------
__global__ void __launch_bounds__(256) k_edge1(int E) {
    long long t = (long long)blockIdx.x * blockDim.x + threadIdx.x;
    long long e = t >> 3;
    int f4 = (int)(t & 7);
    if (e >= E) return;
    uint2 r = g_pack[e];
    int src = r.x & 0xffff;
    int dst = r.x >> 16;
    int k0  = r.y & 3;
    int k1  = min(k0 + 1, KS - 1);
    float f = __uint_as_float(r.y & ~3u);
    const __half* base = g_xw1h + src * 128;
    uint2 pa = *(const uint2*)(base + k0 * 32 + f4 * 4);
    uint2 pb = *(const uint2*)(base + k1 * 32 + f4 * 4);
    float2 A0 = __half22float2(*(const __half2*)&pa.x);
    float2 A1 = __half22float2(*(const __half2*)&pa.y);
    float2 B0 = __half22float2(*(const __half2*)&pb.x);
    float2 B1 = __half22float2(*(const __half2*)&pb.y);
    float w0 = 1.0f - f;
    float4 m = make_float4(w0 * A0.x + f * B0.x, w0 * A0.y + f * B0.y,
                           w0 * A1.x + f * B1.x, w0 * A1.y + f * B1.y);
    red_add_v4(&g_agg1[dst * HID + f4 * 4], m);
}

// ---------------- layer-1 epilogue: h = elu(agg1/deg + rb1) ------------------------
__global__ void k_h(int N) {
    int i = blockIdx.x * blockDim.x + threadIdx.x;
    if (i >= N * HID) return;
    int n = i >> 5;
    float d = fmaxf(g_deg[n], 1.0f);
    float v = g_agg1[i] / d + g_rb1[i];
    g_h[i] = (v > 0.f) ? v : expm1f(v);
}

// ---------------- layer-2 node GEMM (f32x2) ----------------------------------------
__global__ void __launch_bounds__(64) k_prep2(const float* __restrict__ W2,
                                              const float* __restrict__ root2,
                                              const float* __restrict__ bias2, int N) {
    const int j = threadIdx.x;          // active j<50
    bool active = (j < 50);
    float wcol[HID];
    float binit = 0.f;
    if (j < 40) {
        int k = j / NCLS, c = j % NCLS;
        #pragma unroll
        for (int o = 0; o < HID; o++) wcol[o] = W2[(k * HID + o) * NCLS + c];
    } else if (j < 50) {
        int c = j - 40;
        #pragma unroll
        for (int o = 0; o < HID; o++) wcol[o] = root2[o * NCLS + c];
        binit = bias2[c];
    }
    __shared__ __align__(16) float hs[HID * NB];
    int ntiles = (N + NB - 1) / NB;
    for (int tile = blockIdx.x; tile < ntiles; tile += gridDim.x) {
        int n0 = tile * NB;
        __syncthreads();
        for (int idx = j; idx < HID * NB; idx += 64) {
            int nn = idx / HID, o = idx % HID;
            int n = n0 + nn;
            hs[o * NB + nn] = (n < N) ? g_h[n * HID + o] : 0.f;
        }
        __syncthreads();
        if (active) {
            unsigned long long acc2[NB / 2];
            unsigned long long binit2 = pack2(binit);
            #pragma unroll
            for (int p = 0; p < NB / 2; p++) acc2[p] = binit2;
            #pragma unroll
            for (int o = 0; o < HID; o++) {
                unsigned long long w2 = pack2(wcol[o]);
                #pragma unroll
                for (int q = 0; q < NB / 4; q++) {
                    ulonglong2 hv = *(const ulonglong2*)&hs[o * NB + q * 4];
                    ffma2(acc2[q * 2],     hv.x, w2);
                    ffma2(acc2[q * 2 + 1], hv.y, w2);
                }
            }
            #pragma unroll
            for (int p = 0; p < NB / 2; p++) {
                float2 v = unpack2(acc2[p]);
                int na = n0 + p * 2, nb2 = na + 1;
                if (na < N) {
                    if (j < 40) g_xw2h[na * 40 + j]         = __float2half(v.x);
                    else        g_rb2[na * NCLS + (j - 40)] = v.x;
                }
                if (nb2 < N) {
                    if (j < 40) g_xw2h[nb2 * 40 + j]         = __float2half(v.y);
                    else        g_rb2[nb2 * NCLS + (j - 40)] = v.y;
                }
            }
        }
    }
}

// ---------------- layer-2 edge scatter: 6 edges/warp x 5 lanes (float2) -----------
__global__ void __launch_bounds__(256) k_edge2(int E) {
    int t = blockIdx.x * blockDim.x + threadIdx.x;
    int lane = t & 31;
    int wid = t >> 5;
    int eg = lane / 5;
    int j  = lane - eg * 5;
    if (eg >= 6) return;
    long long e = (long long)wid * 6 + eg;
    if (e >= E) return;
    uint2 r = g_pack[e];
    int src = r.x & 0xffff;
    int dst = r.x >> 16;
    int k0  = r.y & 3;
    int k1  = min(k0 + 1, KS - 1);
    float f = __uint_as_float(r.y & ~3u);
    const __half* base = g_xw2h + src * 40;
    unsigned pa = *(const unsigned*)(base + k0 * 10 + j * 2);
    unsigned pb = *(const unsigned*)(base + k1 * 10 + j * 2);
    float2 A = __half22float2(*(const __half2*)&pa);
    float2 B = __half22float2(*(const __half2*)&pb);
    float w0 = 1.0f - f;
    float2 m = make_float2(w0 * A.x + f * B.x, w0 * A.y + f * B.y);
    red_add_v2(&g_agg2[dst * NCLS + j * 2], m);
}

// ---------------- final: mean + root + bias + log_softmax -------------------------
__global__ void k_out(float* __restrict__ out, int N) {
    int n = blockIdx.x * blockDim.x + threadIdx.x;
    if (n >= N) return;
    float inv = 1.0f / fmaxf(g_deg[n], 1.0f);
    float v[NCLS];
    float mx = -1e30f;
    #pragma unroll
    for (int c = 0; c < NCLS; c++) {
        v[c] = g_agg2[n * NCLS + c] * inv + g_rb2[n * NCLS + c];
        mx = fmaxf(mx, v[c]);
    }
    float s = 0.f;
    #pragma unroll
    for (int c = 0; c < NCLS; c++) s += expf(v[c] - mx);
    float ls = logf(s) + mx;
    #pragma unroll
    for (int c = 0; c < NCLS; c++) out[n * NCLS + c] = v[c] - ls;
}

// ---------------- launch -----------------------------------------------------------
extern "C" void kernel_launch(void* const* d_in, const int* in_sizes, int n_in,
                              void* d_out, int out_size) {
    const float* x     = (const float*)d_in[0];
    const void*  ei    =               d_in[1];
    const float* ea    = (const float*)d_in[2];
    const float* W1    = (const float*)d_in[3];
    const float* root1 = (const float*)d_in[4];
    const float* bias1 = (const float*)d_in[5];
    const float* W2    = (const float*)d_in[6];
    const float* root2 = (const float*)d_in[7];
    const float* bias2 = (const float*)d_in[8];
    float* out = (float*)d_out;

    int N = in_sizes[0] / FIN;     // 50000
    int E = in_sizes[2];           // 1600000

    k_detect<<<1, 32>>>(ei);
    k_zero<<<(N * (HID + NCLS + 1) + 255) / 256, 256>>>(N);
    k_pack<<<(E + 255) / 256, 256>>>(ei, ea, E);
    k_xw1<<<592, J1>>>(x, W1, root1, bias1, N);
    long long th1 = (long long)E * 8;
    k_edge1<<<(int)((th1 + 255) / 256), 256>>>(E);
    k_h<<<(N * HID + 255) / 256, 256>>>(N);
    k_prep2<<<1184, 64>>>(W2, root2, bias2, N);
    int warps2 = (E + 5) / 6;
    k_edge2<<<(warps2 + 7) / 8, 256>>>(E);
    k_out<<<(N + 255) / 256, 256>>>(out, N);
}